// round 17
// baseline (speedup 1.0000x reference)
#include <cuda_runtime.h>
#include <cstdint>

// SVConv2d: out[n,o,h,w] = bias[o] + sum_{ci,kh,kw} x[n,ci,h+kh-1,w+kw-1] * W[o,ci,kh,kw,h,w]
// N=8, Cin=Cout=32, K=3, H=W=64. Weight (151 MB) streams once -> DRAM-bound.
// R17: R16 with the missing <cstdint> fixed. Weight double-buffer in smem via
// cp.async (zero register occupancy in flight) -> regs drop, 6 CTAs/SM, 24
// warps of latency hiding. Per-thread-private smem slots (stride 37,
// conflict-free), no barriers. CPB=4, SPLIT=4, fused prep, atomics epilogue.

typedef unsigned long long ull;

#define HW 4096
#define PD 66            // padded spatial dim
#define PP (PD * PD)     // 4356
#define SPLIT 4
#define CPB 4
#define CINS (32 / SPLIT)   // 8 cins per block
#define WSTR 37          // padded slot stride (37 mod 32 = 5, coprime with 32)

// scratch (allocation-free: __device__ globals)
__device__ float4 g_xp0[32 * PP];              // (cin, 66, 66) n0..3 : 2.2 MB
__device__ float4 g_xp1[32 * PP];              // (cin, 66, 66) n4..7 : 2.2 MB

__device__ __forceinline__ ull pack2(float a, float b) {
    ull r; asm("mov.b64 %0, {%1, %2};" : "=l"(r) : "f"(a), "f"(b)); return r;
}
__device__ __forceinline__ void fma2(ull& d, ull a, ull b) {
    asm("fma.rn.f32x2 %0, %1, %2, %0;" : "+l"(d) : "l"(a), "l"(b));
}
__device__ __forceinline__ float2 unpack2(ull v) {
    float x, y; asm("mov.b64 {%0, %1}, %2;" : "=f"(x), "=f"(y) : "l"(v));
    return make_float2(x, y);
}
__device__ __forceinline__ void cpa4(unsigned int s, const float* g) {
    asm volatile("cp.async.ca.shared.global [%0], [%1], 4;" :: "r"(s), "l"(g));
}
#define CP_COMMIT() asm volatile("cp.async.commit_group;" ::: "memory")
#define CP_WAIT1()  asm volatile("cp.async.wait_group 1;" ::: "memory")
#define CP_WAIT0()  asm volatile("cp.async.wait_group 0;" ::: "memory")

// ---- kernel 1: fused prep (out=bias init + x transpose + border zero) ----
__global__ __launch_bounds__(256) void prep_all(const float* __restrict__ x,
                                                const float* __restrict__ bias,
                                                float4* __restrict__ out) {
    int idx = blockIdx.x * 256 + threadIdx.x;      // < 262144

    float b = __ldg(bias + ((idx >> 10) & 31));
    out[idx] = make_float4(b, b, b, b);

    int item = idx >> 3, n = idx & 7;              // 32768 items x 8 n
    int cin = item >> 10;
    int rem = item & 1023;
    int h = rem >> 4;
    int w4 = (rem & 15) * 4;
    float4 v = *(const float4*)(x + (size_t)(n * 32 + cin) * HW + h * 64 + w4);
    float4* base = ((n < 4) ? g_xp0 : g_xp1) + (size_t)cin * PP + (h + 1) * PD + (w4 + 1);
    int comp = n & 3;
    ((float*)(base + 0))[comp] = v.x;
    ((float*)(base + 1))[comp] = v.y;
    ((float*)(base + 2))[comp] = v.z;
    ((float*)(base + 3))[comp] = v.w;

    if (idx < 32 * 260) {                          // border (260 cells per cin)
        int bc = idx / 260, r = idx - bc * 260;
        int hp, wp;
        if (r < 66)       { hp = 0;            wp = r; }
        else if (r < 132) { hp = 65;           wp = r - 66; }
        else if (r < 196) { hp = r - 132 + 1;  wp = 0; }
        else              { hp = r - 196 + 1;  wp = 65; }
        float4 z = make_float4(0.f, 0.f, 0.f, 0.f);
        g_xp0[bc * PP + hp * PD + wp] = z;
        g_xp1[bc * PP + hp * PD + wp] = z;
    }
}

// issue 36 async weight copies (9 taps x 4 couts) into this thread's slot
__device__ __forceinline__ void loadW_async(unsigned int slot_s, const float* wp) {
#pragma unroll
    for (int c = 0; c < CPB; c++)
#pragma unroll
        for (int t = 0; t < 9; t++)
            cpa4(slot_s + (c * 9 + t) * 4,
                 wp + (size_t)c * (32 * 9 * HW) + t * HW);
}

// consume one cin: weights from this thread's smem slot
__device__ __forceinline__ void fmaTaps(const float* wb,
                                        const float4* xb0, const float4* xb1,
                                        ull acc[CPB][4]) {
#pragma unroll
    for (int t = 0; t < 9; t++) {
        const int off = (t / 3 - 1) * PD + (t % 3 - 1);  // compile-time
        float4 lo = __ldg(xb0 + off);
        float4 hi = __ldg(xb1 + off);
        ull xq0 = pack2(lo.x, lo.y);
        ull xq1 = pack2(lo.z, lo.w);
        ull xq2 = pack2(hi.x, hi.y);
        ull xq3 = pack2(hi.z, hi.w);
#pragma unroll
        for (int c = 0; c < CPB; c++) {
            float wv = wb[c * 9 + t];
            ull wd = pack2(wv, wv);
            fma2(acc[c][0], wd, xq0);
            fma2(acc[c][1], wd, xq1);
            fma2(acc[c][2], wd, xq2);
            fma2(acc[c][3], wd, xq3);
        }
    }
}

// ---- kernel 2: main. block (32,4); warp = 32 consecutive w; no __syncthreads ----
__global__ __launch_bounds__(128, 6) void svconv_main(const float* __restrict__ wt_g,
                                                      float* __restrict__ out) {
    __shared__ float ws[2][128][WSTR];             // 37,888 B

    const int lane = threadIdx.x, row = threadIdx.y;
    const int tid = row * 32 + lane;
    const int px = blockIdx.x * 32 + lane;
    const int py = blockIdx.y * 4 + row;
    const int c0 = (blockIdx.z & 7) * CPB;         // cout group (4 couts)
    const int s = blockIdx.z >> 3;                 // cin quarter

    ull acc[CPB][4];
#pragma unroll
    for (int c = 0; c < CPB; c++)
#pragma unroll
        for (int j = 0; j < 4; j++) acc[c][j] = 0ull;

    const float4* xb0 = g_xp0 + (size_t)(s * CINS) * PP + (py + 1) * PD + (px + 1);
    const float4* xb1 = g_xp1 + (size_t)(s * CINS) * PP + (py + 1) * PD + (px + 1);
    const float* wp = wt_g + (size_t)(c0 * 32 + s * CINS) * 9 * HW + py * 64 + px;

    const float* slot0 = &ws[0][tid][0];
    const float* slot1 = &ws[1][tid][0];
    const unsigned int s0 = (unsigned int)__cvta_generic_to_shared(slot0);
    const unsigned int s1 = (unsigned int)__cvta_generic_to_shared(slot1);

    loadW_async(s0, wp);                           // cin 0 -> buf0
    CP_COMMIT();

#pragma unroll 1
    for (int ci = 0; ci < CINS - 1; ci++) {
        // prefetch cin+1 into the other buffer
        loadW_async((ci & 1) ? s0 : s1, wp + (size_t)9 * HW);
        CP_COMMIT();
        CP_WAIT1();                                // current cin's group done
        fmaTaps((ci & 1) ? slot1 : slot0, xb0, xb1, acc);
        xb0 += PP; xb1 += PP;
        wp += (size_t)9 * HW;
    }
    CP_WAIT0();
    fmaTaps(((CINS - 1) & 1) ? slot1 : slot0, xb0, xb1, acc);  // last cin

    // ---- epilogue: atomic accumulate into out (bias pre-added by prep) ----
    float* ob = out + (size_t)c0 * HW + py * 64 + px;
#pragma unroll
    for (int c = 0; c < CPB; c++)
#pragma unroll
        for (int j = 0; j < 4; j++) {
            float2 v = unpack2(acc[c][j]);
            int n0 = 2 * j, n1 = 2 * j + 1;
            atomicAdd(ob + (((size_t)n0 * 32) + c) * HW, v.x);
            atomicAdd(ob + (((size_t)n1 * 32) + c) * HW, v.y);
        }
}

extern "C" void kernel_launch(void* const* d_in, const int* in_sizes, int n_in,
                              void* d_out, int out_size) {
    const float* x = (const float*)d_in[0];
    const float* wgt = (const float*)d_in[1];
    const float* bias = (const float*)d_in[2];
    float* out = (float*)d_out;

    prep_all<<<(8 * 32 * HW / 4) / 256, 256>>>(x, bias, (float4*)out);
    dim3 grid(2, 16, 8 * SPLIT);                   // 2 x 16 x 32 = 1024 blocks
    dim3 block(32, 4);                             // 128 threads
    svconv_main<<<grid, block>>>(wgt, out);
}